// round 1
// baseline (speedup 1.0000x reference)
#include <cuda_runtime.h>
#include <cstdint>

// ============================================================================
// EdgeAttentionEmbedding — collapsed algebra version.
//
// Reference collapses (softmax([s,s]) == [0.5,0.5] always, so the attention
// branch W2/b2/Wa/ba is dead) to:
//   out[e] = softmax( c_e*(p[u]+p[v]) + ef[e]@Wb + bconst ),  c_e = (u==v)?1:0.5
//   p[n]   = node_features[n] @ M
//   M      = 0.5 * sum_h W1_h @ W3_h[:128]
//   Wb     = 0.5 * sum_h W3_h[128:192]
//   bconst = sum_h b1_h @ W3_h[:128] + 0.5 * sum_h b3_h
// ============================================================================

#define MAXN 50176  // >= N (50000)

__device__ float g_M[128 * 128];
__device__ float g_Wb[64 * 128];
__device__ float g_bc[128];
__device__ float g_p[(size_t)MAXN * 128];

// ---------------------------------------------------------------------------
// Prep: fold the per-head weights into M, Wb, bconst. Tiny (runs in ~2us).
// blocks 0..127: M row i.  block 128: Wb + bconst.
// ---------------------------------------------------------------------------
__global__ void prep_kernel(const float* __restrict__ W1,
                            const float* __restrict__ b1,
                            const float* __restrict__ W3,
                            const float* __restrict__ b3) {
    int j = threadIdx.x;           // 0..127 output column
    int blk = blockIdx.x;
    if (blk < 128) {
        int i = blk;
        float acc = 0.f;
        #pragma unroll
        for (int h = 0; h < 2; h++) {
            const float* w1r = W1 + ((size_t)h * 128 + i) * 128;
            const float* w3  = W3 + (size_t)h * 192 * 128;
            #pragma unroll 8
            for (int k = 0; k < 128; k++)
                acc += w1r[k] * w3[k * 128 + j];
        }
        g_M[i * 128 + j] = 0.5f * acc;
    } else {
        // Wb: rows 128..191 of W3, averaged over heads
        for (int r = 0; r < 64; r++) {
            float wv = 0.5f * (W3[(size_t)(128 + r) * 128 + j] +
                               W3[(size_t)192 * 128 + (size_t)(128 + r) * 128 + j]);
            g_Wb[r * 128 + j] = wv;
        }
        float a1 = 0.f, a2 = 0.f;
        #pragma unroll
        for (int h = 0; h < 2; h++) {
            const float* w3 = W3 + (size_t)h * 192 * 128;
            #pragma unroll 8
            for (int k = 0; k < 128; k++)
                a1 += b1[h * 128 + k] * w3[k * 128 + j];
            a2 += b3[h * 128 + j];
        }
        g_bc[j] = a1 + 0.5f * a2;
    }
}

// ---------------------------------------------------------------------------
// Packed f32x2 helpers (Blackwell packed fp32: 2 MACs per FFMA2 issue)
// ---------------------------------------------------------------------------
__device__ __forceinline__ unsigned long long pack2(float a, float b) {
    unsigned long long r;
    asm("mov.b64 %0,{%1,%2};" : "=l"(r) : "r"(__float_as_uint(a)), "r"(__float_as_uint(b)));
    return r;
}
__device__ __forceinline__ unsigned long long dup2(float a) {
    unsigned long long r;
    unsigned int u = __float_as_uint(a);
    asm("mov.b64 %0,{%1,%1};" : "=l"(r) : "r"(u));
    return r;
}
__device__ __forceinline__ void unpack2(unsigned long long p, float& a, float& b) {
    unsigned int u0, u1;
    asm("mov.b64 {%0,%1},%2;" : "=r"(u0), "=r"(u1) : "l"(p));
    a = __uint_as_float(u0);
    b = __uint_as_float(u1);
}
__device__ __forceinline__ void fma2(unsigned long long& acc,
                                     unsigned long long a, unsigned long long b) {
    asm("fma.rn.f32x2 %0, %1, %2, %0;" : "+l"(acc) : "l"(a), "l"(b));
}

// ---------------------------------------------------------------------------
// Node transform: p = node_features @ M.  [N,128] @ [128,128]
// Block = 256 thr, 32 nodes. Warp handles 4 nodes; lane owns 4 cols.
// M loaded in two 64-row halves (keeps static smem at exactly 48KB).
// ---------------------------------------------------------------------------
__global__ __launch_bounds__(256) void node_kernel(const float* __restrict__ x, int N) {
    __shared__ float sM[64 * 128];   // 32KB (current K-half of M)
    __shared__ float sx[32 * 128];   // 16KB node tile

    int tid = threadIdx.x;
    int n_base = blockIdx.x * 32;
    int lane = tid & 31, w = tid >> 5;
    int j = lane << 2;       // output cols j..j+3
    int n0 = w << 2;         // local nodes n0..n0+3

    // load node tile (zero-padded)
    for (int i = tid; i < 1024; i += 256) {
        int row = i >> 5, col = (i & 31) << 2;
        float4 v = make_float4(0.f, 0.f, 0.f, 0.f);
        if (n_base + row < N) v = *(const float4*)(x + (size_t)(n_base + row) * 128 + col);
        *(float4*)(sx + row * 128 + col) = v;
    }

    unsigned long long acc[4][2];
    #pragma unroll
    for (int e = 0; e < 4; e++) { acc[e][0] = 0ull; acc[e][1] = 0ull; }

    #pragma unroll
    for (int half = 0; half < 2; half++) {
        __syncthreads();
        for (int i = tid; i < 2048; i += 256)
            ((float4*)sM)[i] = ((const float4*)(g_M + half * 64 * 128))[i];
        __syncthreads();
        #pragma unroll 8
        for (int k = 0; k < 64; k++) {
            float4 m4 = *(const float4*)(sM + (k << 7) + j);
            unsigned long long mA = pack2(m4.x, m4.y);
            unsigned long long mB = pack2(m4.z, m4.w);
            #pragma unroll
            for (int e = 0; e < 4; e++) {
                unsigned long long xv = dup2(sx[(n0 + e) * 128 + half * 64 + k]);
                fma2(acc[e][0], xv, mA);
                fma2(acc[e][1], xv, mB);
            }
        }
    }

    #pragma unroll
    for (int e = 0; e < 4; e++) {
        int n = n_base + n0 + e;
        if (n < N) {
            float v0, v1, v2, v3;
            unpack2(acc[e][0], v0, v1);
            unpack2(acc[e][1], v2, v3);
            *(float4*)(g_p + (size_t)n * 128 + j) = make_float4(v0, v1, v2, v3);
        }
    }
}

// ---------------------------------------------------------------------------
// Fused edge kernel: q = ef@Wb; logits = c*(p_u+p_v)+q+bconst; out = softmax.
// Block = 256 thr, 32 edges. Warp handles 4 edges; lane owns 4 cols.
// fma-pipe-bound: 8 FFMA2 / k / thread.
// ---------------------------------------------------------------------------
__global__ __launch_bounds__(256) void edge_kernel(const float* __restrict__ ef,
                                                   const int* __restrict__ ei,
                                                   float* __restrict__ out, int E) {
    __shared__ float sW[64 * 128];  // 32KB Wb
    __shared__ float sE[32 * 64];   // 8KB edge-feature tile
    __shared__ float sB[128];       // bconst

    int tid = threadIdx.x;
    int e_base = blockIdx.x * 32;

    for (int i = tid; i < 2048; i += 256)
        ((float4*)sW)[i] = ((const float4*)g_Wb)[i];
    if (tid < 32)
        *(float4*)(sB + tid * 4) = *(const float4*)(g_bc + tid * 4);
    for (int i = tid; i < 512; i += 256) {
        int row = i >> 4, col = (i & 15) << 2;
        float4 v = make_float4(0.f, 0.f, 0.f, 0.f);
        if (e_base + row < E) v = *(const float4*)(ef + (size_t)(e_base + row) * 64 + col);
        *(float4*)(sE + row * 64 + col) = v;
    }
    __syncthreads();

    int lane = tid & 31, w = tid >> 5;
    int j = lane << 2;     // output cols
    int e0 = w << 2;       // local edges e0..e0+3

    unsigned long long acc[4][2];
    #pragma unroll
    for (int e = 0; e < 4; e++) { acc[e][0] = 0ull; acc[e][1] = 0ull; }

    #pragma unroll 8
    for (int k = 0; k < 64; k++) {
        float4 m4 = *(const float4*)(sW + (k << 7) + j);
        unsigned long long mA = pack2(m4.x, m4.y);
        unsigned long long mB = pack2(m4.z, m4.w);
        #pragma unroll
        for (int e = 0; e < 4; e++) {
            unsigned long long ev = dup2(sE[(e0 + e) * 64 + k]);  // warp-broadcast LDS
            fma2(acc[e][0], ev, mA);
            fma2(acc[e][1], ev, mB);
        }
    }

    float4 bc = *(const float4*)(sB + j);

    #pragma unroll
    for (int e = 0; e < 4; e++) {
        int eg = e_base + e0 + e;
        bool ok = (eg < E);            // uniform across the warp
        int u = 0, vtx = 0;
        if (ok) { u = ei[eg]; vtx = ei[E + eg]; }
        float cf = (u == vtx) ? 1.0f : 0.5f;
        float4 pu = make_float4(0.f, 0.f, 0.f, 0.f), pv = pu;
        if (ok) {
            pu = *(const float4*)(g_p + (size_t)u * 128 + j);
            pv = *(const float4*)(g_p + (size_t)vtx * 128 + j);
        }
        float v0, v1, v2, v3;
        unpack2(acc[e][0], v0, v1);
        unpack2(acc[e][1], v2, v3);
        v0 = fmaf(cf, pu.x + pv.x, v0 + bc.x);
        v1 = fmaf(cf, pu.y + pv.y, v1 + bc.y);
        v2 = fmaf(cf, pu.z + pv.z, v2 + bc.z);
        v3 = fmaf(cf, pu.w + pv.w, v3 + bc.w);

        // softmax over 128 cols spread across the warp (4 per lane)
        float mx = fmaxf(fmaxf(v0, v1), fmaxf(v2, v3));
        #pragma unroll
        for (int off = 16; off > 0; off >>= 1)
            mx = fmaxf(mx, __shfl_xor_sync(0xffffffffu, mx, off));
        v0 = __expf(v0 - mx);
        v1 = __expf(v1 - mx);
        v2 = __expf(v2 - mx);
        v3 = __expf(v3 - mx);
        float s = (v0 + v1) + (v2 + v3);
        #pragma unroll
        for (int off = 16; off > 0; off >>= 1)
            s += __shfl_xor_sync(0xffffffffu, s, off);
        float inv = __fdividef(1.0f, s);
        if (ok)
            *(float4*)(out + (size_t)eg * 128 + j) =
                make_float4(v0 * inv, v1 * inv, v2 * inv, v3 * inv);
    }
}

// ---------------------------------------------------------------------------
extern "C" void kernel_launch(void* const* d_in, const int* in_sizes, int n_in,
                              void* d_out, int out_size) {
    const float* node = (const float*)d_in[0];
    const float* ef   = (const float*)d_in[1];
    const int*   ei   = (const int*)d_in[2];
    const float* W1   = (const float*)d_in[3];
    const float* b1   = (const float*)d_in[4];
    // d_in[5], d_in[6] (W2, b2) are dead code in the reference
    const float* W3   = (const float*)d_in[7];
    const float* b3   = (const float*)d_in[8];
    // d_in[9], d_in[10] (Wa, ba) are dead code in the reference

    int N = in_sizes[0] / 128;
    int E = in_sizes[1] / 64;
    float* out = (float*)d_out;

    prep_kernel<<<129, 128>>>(W1, b1, W3, b3);
    node_kernel<<<(N + 31) / 32, 256>>>(node, N);
    edge_kernel<<<(E + 31) / 32, 256>>>(ef, ei, out, E);
}